// round 1
// baseline (speedup 1.0000x reference)
#include <cuda_runtime.h>

#define N0C 100000
#define N1C 100000
#define KNN 16
#define DM  64
#define DA  32

// Scratch (static __device__ arrays are the sanctioned allocation-free scratch).
// KV0[j][0..31]  = feats0[j]@Wk[0:64] + coords0[j]@Wk[64:67] + bk
// KV0[j][32..95] = feats0[j]@Wv[0:64] + coords0[j]@Wv[64:67] + bv
__device__ float g_KV0[(size_t)N0C * 96];
__device__ float g_Q[(size_t)N1C * 32];

// ---------------------------------------------------------------------------
// Kernel 1: per-source-point KV precompute.  [N0,67] x [67,96] GEMM.
// Block: 256 threads, tile 64 points x 96 cols, per-thread 4p x 6c register tile.
// ---------------------------------------------------------------------------
__global__ __launch_bounds__(256) void kv0_kernel(
    const float* __restrict__ feats0, const float* __restrict__ coords0,
    const float* __restrict__ Wk, const float* __restrict__ bk,
    const float* __restrict__ Wv, const float* __restrict__ bv)
{
    __shared__ float Ws[67][96];
    __shared__ float Bs[96];
    __shared__ float Xs[64][68];   // 67 inputs + pad

    const int t = threadIdx.x;

    for (int idx = t; idx < 67 * 96; idx += 256) {
        int i = idx / 96, c = idx % 96;
        Ws[i][c] = (c < 32) ? Wk[i * 32 + c] : Wv[i * 64 + (c - 32)];
    }
    if (t < 96) Bs[t] = (t < 32) ? bk[t] : bv[t - 32];

    const int base = blockIdx.x * 64;
    for (int idx = t; idx < 64 * 67; idx += 256) {
        int p = idx / 67, i = idx % 67;
        int pt = base + p;
        float v = 0.0f;
        if (pt < N0C)
            v = (i < 64) ? feats0[(size_t)pt * 64 + i] : coords0[(size_t)pt * 3 + (i - 64)];
        Xs[p][i] = v;
    }
    __syncthreads();

    const int tc = t & 15;          // 16 column groups
    const int tp = t >> 4;          // 16 point groups
    const int c0 = tc * 6;
    const int p0 = tp * 4;

    float acc[4][6];
#pragma unroll
    for (int pp = 0; pp < 4; pp++)
#pragma unroll
        for (int cc = 0; cc < 6; cc++)
            acc[pp][cc] = Bs[c0 + cc];

#pragma unroll 4
    for (int i = 0; i < 67; i++) {
        float xa[4], wa[6];
#pragma unroll
        for (int pp = 0; pp < 4; pp++) xa[pp] = Xs[p0 + pp][i];
#pragma unroll
        for (int cc = 0; cc < 6; cc++) wa[cc] = Ws[i][c0 + cc];
#pragma unroll
        for (int pp = 0; pp < 4; pp++)
#pragma unroll
            for (int cc = 0; cc < 6; cc++)
                acc[pp][cc] = fmaf(xa[pp], wa[cc], acc[pp][cc]);
    }

#pragma unroll
    for (int pp = 0; pp < 4; pp++) {
        int pt = base + p0 + pp;
        if (pt < N0C) {
            float* dst = g_KV0 + (size_t)pt * 96 + c0;
#pragma unroll
            for (int cc = 0; cc < 6; cc++) dst[cc] = acc[pp][cc];
        }
    }
}

// ---------------------------------------------------------------------------
// Kernel 2: Q projection.  [N1,64] x [64,32] GEMM.
// Block: 256 threads, tile 64 points x 32 cols, per-thread 4p x 2c.
// ---------------------------------------------------------------------------
__global__ __launch_bounds__(256) void q_kernel(
    const float* __restrict__ feats1,
    const float* __restrict__ Wq, const float* __restrict__ bq)
{
    __shared__ float Ws[64][32];
    __shared__ float Bs[32];
    __shared__ float Xs[64][65];

    const int t = threadIdx.x;

    for (int idx = t; idx < 64 * 32; idx += 256)
        (&Ws[0][0])[idx] = Wq[idx];
    if (t < 32) Bs[t] = bq[t];

    const int base = blockIdx.x * 64;
    for (int idx = t; idx < 64 * 64; idx += 256) {
        int p = idx >> 6, i = idx & 63;
        int pt = base + p;
        Xs[p][i] = (pt < N1C) ? feats1[(size_t)pt * 64 + i] : 0.0f;
    }
    __syncthreads();

    const int tc = t & 15;
    const int tp = t >> 4;
    const int c0 = tc * 2;
    const int p0 = tp * 4;

    float acc[4][2];
#pragma unroll
    for (int pp = 0; pp < 4; pp++) {
        acc[pp][0] = Bs[c0];
        acc[pp][1] = Bs[c0 + 1];
    }

#pragma unroll 8
    for (int i = 0; i < 64; i++) {
        float w0 = Ws[i][c0], w1 = Ws[i][c0 + 1];
#pragma unroll
        for (int pp = 0; pp < 4; pp++) {
            float x = Xs[p0 + pp][i];
            acc[pp][0] = fmaf(x, w0, acc[pp][0]);
            acc[pp][1] = fmaf(x, w1, acc[pp][1]);
        }
    }

#pragma unroll
    for (int pp = 0; pp < 4; pp++) {
        int pt = base + p0 + pp;
        if (pt < N1C) {
            g_Q[(size_t)pt * 32 + c0]     = acc[pp][0];
            g_Q[(size_t)pt * 32 + c0 + 1] = acc[pp][1];
        }
    }
}

// ---------------------------------------------------------------------------
// Kernel 3: gather + attention.  64 threads per query (thread = h*16+k for the
// logit phase and = output dim d for the AV phase), 8 queries per 512-thr block.
// out[n][d] = sum_k a[h(d)][k] * KV0[idx_k][32+d]  -  coords1[n] @ Wv[64:67, d]
// ---------------------------------------------------------------------------
__global__ __launch_bounds__(512) void attn_kernel(
    const float* __restrict__ coords1,
    const int*   __restrict__ knn,
    const float* __restrict__ Wv,
    float*       __restrict__ out)
{
    __shared__ float sQ[8][32];
    __shared__ int   sIdx[8][16];
    __shared__ float sC1[8][3];
    __shared__ float sWvc[3][64];

    const int tid = threadIdx.x;
    if (tid < 192) sWvc[tid / 64][tid % 64] = Wv[(size_t)(64 + tid / 64) * 64 + (tid % 64)];

    const int q   = tid >> 6;      // query slot in block
    const int t64 = tid & 63;
    const int n   = blockIdx.x * 8 + q;   // N1C % 8 == 0 -> no guard

    if (t64 < 32)       sQ[q][t64]        = g_Q[(size_t)n * 32 + t64];
    else if (t64 < 48)  sIdx[q][t64 - 32] = knn[(size_t)n * 16 + (t64 - 32)];
    else if (t64 < 51)  sC1[q][t64 - 48]  = coords1[(size_t)n * 3 + (t64 - 48)];
    __syncthreads();

    const int h  = t64 >> 4;
    const int kk = t64 & 15;

    // logit for (head h, neighbor kk)
    const int j = sIdx[q][kk];
    const float4* kp = reinterpret_cast<const float4*>(g_KV0 + (size_t)j * 96 + h * 8);
    float4 ka = kp[0], kb = kp[1];
    const float4* qp = reinterpret_cast<const float4*>(&sQ[q][h * 8]);
    float4 qa = qp[0], qb = qp[1];

    float logit = ka.x * qa.x + ka.y * qa.y + ka.z * qa.z + ka.w * qa.w
                + kb.x * qb.x + kb.y * qb.y + kb.z * qb.z + kb.w * qb.w;
    logit *= 0.35355339059327373f;   // 1/sqrt(8)

    // softmax over the 16 lanes sharing this head (xor widths stay in-group)
    float m = logit;
#pragma unroll
    for (int off = 8; off; off >>= 1)
        m = fmaxf(m, __shfl_xor_sync(0xffffffffu, m, off));
    float e = __expf(logit - m);
    float s = e;
#pragma unroll
    for (int off = 8; off; off >>= 1)
        s += __shfl_xor_sync(0xffffffffu, s, off);
    float a = e / s;

    // AV: this thread owns output dim d = t64 (head = t64>>4, vdim = t64&15).
    const int srcHi = t64 & 16;   // warp-local base lane of this head's group
    float acc = 0.0f;
#pragma unroll
    for (int kp_ = 0; kp_ < 16; kp_++) {
        float aj = __shfl_sync(0xffffffffu, a, srcHi | kp_);
        int jj = sIdx[q][kp_];
        acc = fmaf(aj, g_KV0[(size_t)jj * 96 + 32 + t64], acc);
    }

    float cv = sC1[q][0] * sWvc[0][t64]
             + sC1[q][1] * sWvc[1][t64]
             + sC1[q][2] * sWvc[2][t64];

    out[(size_t)n * 64 + t64] = acc - cv;
}

// ---------------------------------------------------------------------------
// Kernel 4: knn_idxs passthrough tail (reference returns the tuple's 2nd elem).
// ---------------------------------------------------------------------------
__global__ void idx_copy_kernel(const int* __restrict__ knn, float* __restrict__ out, int n)
{
    int i = blockIdx.x * blockDim.x + threadIdx.x;
    if (i < n) out[i] = (float)knn[i];
}

extern "C" void kernel_launch(void* const* d_in, const int* in_sizes, int n_in,
                              void* d_out, int out_size)
{
    const float* coords0 = (const float*)d_in[0];
    const float* coords1 = (const float*)d_in[1];
    const float* feats0  = (const float*)d_in[2];
    const float* feats1  = (const float*)d_in[3];
    const int*   knn     = (const int*)  d_in[4];
    const float* Wq      = (const float*)d_in[5];
    const float* bq      = (const float*)d_in[6];
    const float* Wk      = (const float*)d_in[7];
    const float* bk      = (const float*)d_in[8];
    const float* Wv      = (const float*)d_in[9];
    const float* bv      = (const float*)d_in[10];
    float* out = (float*)d_out;

    kv0_kernel<<<(N0C + 63) / 64, 256>>>(feats0, coords0, Wk, bk, Wv, bv);
    q_kernel  <<<(N1C + 63) / 64, 256>>>(feats1, Wq, bq);
    attn_kernel<<<N1C / 8, 512>>>(coords1, knn, Wv, out);

    int tail = out_size - N1C * DM;
    if (tail > 0) {
        idx_copy_kernel<<<(tail + 255) / 256, 256>>>(knn, out + (size_t)N1C * DM, tail);
    }
}

// round 2
// speedup vs baseline: 1.0660x; 1.0660x over previous
#include <cuda_runtime.h>

#define N0C 100000
#define N1C 100000
#define KNN 16
#define DM  64
#define DA  32

#define KV_BLOCKS ((N0C + 63) / 64)   // 1563
#define Q_BLOCKS  ((N1C + 63) / 64)   // 1563

// Scratch (static __device__ arrays are the sanctioned allocation-free scratch).
// KV0[j][0..31]  = feats0[j]@Wk[0:64] + coords0[j]@Wk[64:67] + bk
// KV0[j][32..95] = feats0[j]@Wv[0:64] + coords0[j]@Wv[64:67] + bv
__device__ float g_KV0[(size_t)N0C * 96];
__device__ float g_Q[(size_t)N1C * 32];

// ---------------------------------------------------------------------------
// Fused prep kernel: blocks [0, KV_BLOCKS) do the KV0 GEMM, blocks
// [KV_BLOCKS, KV_BLOCKS+Q_BLOCKS) do the Q GEMM, the rest do the idx copy.
// ---------------------------------------------------------------------------
__global__ __launch_bounds__(256) void prep_kernel(
    const float* __restrict__ feats0, const float* __restrict__ coords0,
    const float* __restrict__ Wk, const float* __restrict__ bk,
    const float* __restrict__ Wv, const float* __restrict__ bv,
    const float* __restrict__ feats1,
    const float* __restrict__ Wq, const float* __restrict__ bq,
    const int*   __restrict__ knn, float* __restrict__ outTail, int tailN)
{
    __shared__ float smem[67 * 96 + 96 + 67 * 68];   // 43.8 KB, unioned across roles
    const int t = threadIdx.x;

    if (blockIdx.x < KV_BLOCKS) {
        // ---------------- KV0: [64 pts, 67 in] x [67, 96 out] ----------------
        float (*Ws)[96] = (float (*)[96])smem;            // weights [i][c]
        float* Bs       = smem + 67 * 96;                 // bias [96]
        float (*Xs)[68] = (float (*)[68])(smem + 67 * 96 + 96); // inputs [i][p] (transposed)

        for (int idx = t; idx < 67 * 96; idx += 256) {
            int i = idx / 96, c = idx % 96;
            Ws[i][c] = (c < 32) ? Wk[i * 32 + c] : Wv[i * 64 + (c - 32)];
        }
        if (t < 96) Bs[t] = (t < 32) ? bk[t] : bv[t - 32];

        const int base = blockIdx.x * 64;
        for (int idx = t; idx < 64 * 67; idx += 256) {
            int p = idx / 67, i = idx % 67;           // i fastest -> coalesced gmem
            int pt = base + p;
            float v = 0.0f;
            if (pt < N0C)
                v = (i < 64) ? feats0[(size_t)pt * 64 + i] : coords0[(size_t)pt * 3 + (i - 64)];
            Xs[i][p] = v;
        }
        __syncthreads();

        const int tc = t & 15;          // 16 column groups of 6
        const int tp = t >> 4;          // 16 point groups of 4
        const int c0 = tc * 6;
        const int p0 = tp * 4;

        float acc[4][6];
#pragma unroll
        for (int pp = 0; pp < 4; pp++)
#pragma unroll
            for (int cc = 0; cc < 6; cc++)
                acc[pp][cc] = Bs[c0 + cc];

#pragma unroll 4
        for (int i = 0; i < 67; i++) {
            const float4 xv  = *(const float4*)&Xs[i][p0];              // LDS.128
            const float2 w01 = *(const float2*)&Ws[i][c0];              // LDS.64 x3
            const float2 w23 = *(const float2*)&Ws[i][c0 + 2];
            const float2 w45 = *(const float2*)&Ws[i][c0 + 4];
            const float xa[4] = {xv.x, xv.y, xv.z, xv.w};
            const float wa[6] = {w01.x, w01.y, w23.x, w23.y, w45.x, w45.y};
#pragma unroll
            for (int pp = 0; pp < 4; pp++)
#pragma unroll
                for (int cc = 0; cc < 6; cc++)
                    acc[pp][cc] = fmaf(xa[pp], wa[cc], acc[pp][cc]);
        }

#pragma unroll
        for (int pp = 0; pp < 4; pp++) {
            int pt = base + p0 + pp;
            if (pt < N0C) {
                float* dst = g_KV0 + (size_t)pt * 96 + c0;
                *(float2*)(dst)     = make_float2(acc[pp][0], acc[pp][1]);
                *(float2*)(dst + 2) = make_float2(acc[pp][2], acc[pp][3]);
                *(float2*)(dst + 4) = make_float2(acc[pp][4], acc[pp][5]);
            }
        }
    } else if (blockIdx.x < KV_BLOCKS + Q_BLOCKS) {
        // ---------------- Q: [64 pts, 64 in] x [64, 32 out] ----------------
        float (*Ws)[32] = (float (*)[32])smem;                  // [64][32]
        float* Bs       = smem + 64 * 32;                       // [32]
        float (*Xs)[68] = (float (*)[68])(smem + 64 * 32 + 32); // [i][p] transposed

        for (int idx = t; idx < 64 * 32; idx += 256)
            (&Ws[0][0])[idx] = Wq[idx];
        if (t < 32) Bs[t] = bq[t];

        const int base = (blockIdx.x - KV_BLOCKS) * 64;
        for (int idx = t; idx < 64 * 64; idx += 256) {
            int p = idx >> 6, i = idx & 63;
            int pt = base + p;
            Xs[i][p] = (pt < N1C) ? feats1[(size_t)pt * 64 + i] : 0.0f;
        }
        __syncthreads();

        const int tc = t & 15;          // 16 col groups of 2
        const int tp = t >> 4;          // 16 point groups of 4
        const int c0 = tc * 2;
        const int p0 = tp * 4;

        float acc[4][2];
#pragma unroll
        for (int pp = 0; pp < 4; pp++) {
            acc[pp][0] = Bs[c0];
            acc[pp][1] = Bs[c0 + 1];
        }

#pragma unroll 8
        for (int i = 0; i < 64; i++) {
            const float4 xv = *(const float4*)&Xs[i][p0];
            const float2 w  = *(const float2*)&Ws[i][c0];
            const float xa[4] = {xv.x, xv.y, xv.z, xv.w};
#pragma unroll
            for (int pp = 0; pp < 4; pp++) {
                acc[pp][0] = fmaf(xa[pp], w.x, acc[pp][0]);
                acc[pp][1] = fmaf(xa[pp], w.y, acc[pp][1]);
            }
        }

#pragma unroll
        for (int pp = 0; pp < 4; pp++) {
            int pt = base + p0 + pp;
            if (pt < N1C)
                *(float2*)(g_Q + (size_t)pt * 32 + c0) = make_float2(acc[pp][0], acc[pp][1]);
        }
    } else {
        // ---------------- knn_idxs passthrough (int -> float) ----------------
        int b = blockIdx.x - KV_BLOCKS - Q_BLOCKS;
        int stride = (gridDim.x - KV_BLOCKS - Q_BLOCKS) * 256;
        for (int i = b * 256 + t; i < tailN; i += stride)
            outTail[i] = (float)knn[i];
    }
}

// ---------------------------------------------------------------------------
// Gather + attention.  64 threads per query (thread = h*16+k for the logit
// phase and = output dim d for the AV phase), 8 queries per 512-thread block.
// out[n][d] = sum_k a[h(d)][k] * KV0[idx_k][32+d]  -  coords1[n] @ Wv[64:67, d]
// ---------------------------------------------------------------------------
__global__ __launch_bounds__(512) void attn_kernel(
    const float* __restrict__ coords1,
    const int*   __restrict__ knn,
    const float* __restrict__ Wv,
    float*       __restrict__ out)
{
    __shared__ float sQ[8][32];
    __shared__ int   sIdx[8][16];
    __shared__ float sC1[8][3];
    __shared__ float sWvc[3][64];

    const int tid = threadIdx.x;
    if (tid < 192) sWvc[tid / 64][tid % 64] = Wv[(size_t)(64 + tid / 64) * 64 + (tid % 64)];

    const int q   = tid >> 6;      // query slot in block
    const int t64 = tid & 63;
    const int n   = blockIdx.x * 8 + q;   // N1C % 8 == 0 -> no guard

    if (t64 < 32)       sQ[q][t64]        = g_Q[(size_t)n * 32 + t64];
    else if (t64 < 48)  sIdx[q][t64 - 32] = knn[(size_t)n * 16 + (t64 - 32)];
    else if (t64 < 51)  sC1[q][t64 - 48]  = coords1[(size_t)n * 3 + (t64 - 48)];
    __syncthreads();

    const int h  = t64 >> 4;
    const int kk = t64 & 15;

    // logit for (head h, neighbor kk)
    const int j = sIdx[q][kk];
    const float4* kp = reinterpret_cast<const float4*>(g_KV0 + (size_t)j * 96 + h * 8);
    float4 ka = kp[0], kb = kp[1];
    const float4* qp = reinterpret_cast<const float4*>(&sQ[q][h * 8]);
    float4 qa = qp[0], qb = qp[1];

    float logit = ka.x * qa.x + ka.y * qa.y + ka.z * qa.z + ka.w * qa.w
                + kb.x * qb.x + kb.y * qb.y + kb.z * qb.z + kb.w * qb.w;
    logit *= 0.35355339059327373f;   // 1/sqrt(8)

    // softmax over the 16 lanes sharing this head (xor widths stay in-group)
    float m = logit;
#pragma unroll
    for (int off = 8; off; off >>= 1)
        m = fmaxf(m, __shfl_xor_sync(0xffffffffu, m, off));
    float e = __expf(logit - m);
    float s = e;
#pragma unroll
    for (int off = 8; off; off >>= 1)
        s += __shfl_xor_sync(0xffffffffu, s, off);
    float a = e / s;

    // AV: this thread owns output dim d = t64 (head = t64>>4, vdim = t64&15).
    const int srcHi = t64 & 16;   // warp-local base lane of this head's group
    float acc = 0.0f;
#pragma unroll
    for (int kp_ = 0; kp_ < 16; kp_++) {
        float aj = __shfl_sync(0xffffffffu, a, srcHi | kp_);
        int jj = sIdx[q][kp_];
        acc = fmaf(aj, g_KV0[(size_t)jj * 96 + 32 + t64], acc);
    }

    float cv = sC1[q][0] * sWvc[0][t64]
             + sC1[q][1] * sWvc[1][t64]
             + sC1[q][2] * sWvc[2][t64];

    out[(size_t)n * 64 + t64] = acc - cv;
}

extern "C" void kernel_launch(void* const* d_in, const int* in_sizes, int n_in,
                              void* d_out, int out_size)
{
    const float* coords0 = (const float*)d_in[0];
    const float* coords1 = (const float*)d_in[1];
    const float* feats0  = (const float*)d_in[2];
    const float* feats1  = (const float*)d_in[3];
    const int*   knn     = (const int*)  d_in[4];
    const float* Wq      = (const float*)d_in[5];
    const float* bq      = (const float*)d_in[6];
    const float* Wk      = (const float*)d_in[7];
    const float* bk      = (const float*)d_in[8];
    const float* Wv      = (const float*)d_in[9];
    const float* bv      = (const float*)d_in[10];
    float* out = (float*)d_out;

    int tail = out_size - N1C * DM;
    if (tail < 0) tail = 0;
    int copyBlocks = tail > 0 ? (tail + 1023) / 1024 : 0;

    prep_kernel<<<KV_BLOCKS + Q_BLOCKS + copyBlocks, 256>>>(
        feats0, coords0, Wk, bk, Wv, bv,
        feats1, Wq, bq,
        knn, out + (size_t)N1C * DM, tail);

    attn_kernel<<<N1C / 8, 512>>>(coords1, knn, Wv, out);
}

// round 3
// speedup vs baseline: 1.8180x; 1.7054x over previous
#include <cuda_runtime.h>
#include <cuda_fp16.h>

#define N0C 100000
#define N1C 100000
#define KNN 16
#define DM  64
#define DA  32

#define KV_BLOCKS ((N0C + 63) / 64)   // 1563
#define Q_BLOCKS  ((N1C + 63) / 64)   // 1563

// Packed-f32x2 helpers (Blackwell FFMA2 path, PTX-only)
#define FFMA2(d, a, b, c) \
    asm("fma.rn.f32x2 %0, %1, %2, %3;" : "=l"(d) : "l"(a), "l"(b), "l"(c))
__device__ __forceinline__ unsigned long long pack2(float lo, float hi) {
    unsigned long long r;
    asm("mov.b64 %0, {%1, %2};" : "=l"(r) : "f"(lo), "f"(hi));
    return r;
}
__device__ __forceinline__ float2 unpack2(unsigned long long v) {
    float2 r;
    asm("mov.b64 {%0, %1}, %2;" : "=f"(r.x), "=f"(r.y) : "l"(v));
    return r;
}

// KV0 in fp16, padded rows of 128 halves (256B, line-aligned):
//   halves [0,32)   : K part  (feats0@Wk[0:64] + coords0@Wk[64:67] + bk)
//   halves [64,128) : V part  (feats0@Wv[0:64] + coords0@Wv[64:67] + bv)
__device__ __half g_KVh[(size_t)N0C * 128];
__device__ float  g_Q[(size_t)N1C * 32];

// ---------------------------------------------------------------------------
// Fused prep kernel: KV0 GEMM blocks, then Q GEMM blocks, then idx-copy blocks.
// ---------------------------------------------------------------------------
__global__ __launch_bounds__(256) void prep_kernel(
    const float* __restrict__ feats0, const float* __restrict__ coords0,
    const float* __restrict__ Wk, const float* __restrict__ bk,
    const float* __restrict__ Wv, const float* __restrict__ bv,
    const float* __restrict__ feats1,
    const float* __restrict__ Wq, const float* __restrict__ bq,
    const int*   __restrict__ knn, float* __restrict__ outTail, int tailN)
{
    __shared__ float smem[67 * 96 + 96 + 67 * 68];
    const int t = threadIdx.x;

    if (blockIdx.x < KV_BLOCKS) {
        // ---------------- KV0: [64 pts, 67 in] x [67, 96 out] ----------------
        float (*Ws)[96] = (float (*)[96])smem;
        float* Bs       = smem + 67 * 96;
        float (*Xs)[68] = (float (*)[68])(smem + 67 * 96 + 96);  // [i][p]

        for (int idx = t; idx < 67 * 96; idx += 256) {
            int i = idx / 96, c = idx % 96;
            Ws[i][c] = (c < 32) ? Wk[i * 32 + c] : Wv[i * 64 + (c - 32)];
        }
        if (t < 96) Bs[t] = (t < 32) ? bk[t] : bv[t - 32];

        const int base = blockIdx.x * 64;
        for (int idx = t; idx < 64 * 67; idx += 256) {
            int p = idx / 67, i = idx % 67;
            int pt = base + p;
            float v = 0.0f;
            if (pt < N0C)
                v = (i < 64) ? feats0[(size_t)pt * 64 + i] : coords0[(size_t)pt * 3 + (i - 64)];
            Xs[i][p] = v;
        }
        __syncthreads();

        const int tc = t & 15;
        const int tp = t >> 4;
        const int c0 = tc * 6;          // even
        const int p0 = tp * 4;

        unsigned long long acc2[4][3];
#pragma unroll
        for (int m = 0; m < 3; m++) {
            unsigned long long b = pack2(Bs[c0 + 2 * m], Bs[c0 + 2 * m + 1]);
#pragma unroll
            for (int pp = 0; pp < 4; pp++) acc2[pp][m] = b;
        }

#pragma unroll 4
        for (int i = 0; i < 67; i++) {
            const float4 xv = *(const float4*)&Xs[i][p0];
            const unsigned long long* wrow = (const unsigned long long*)&Ws[i][c0];
            const unsigned long long w0 = wrow[0], w1 = wrow[1], w2 = wrow[2];
            unsigned long long xx[4];
            xx[0] = pack2(xv.x, xv.x); xx[1] = pack2(xv.y, xv.y);
            xx[2] = pack2(xv.z, xv.z); xx[3] = pack2(xv.w, xv.w);
#pragma unroll
            for (int pp = 0; pp < 4; pp++) {
                FFMA2(acc2[pp][0], xx[pp], w0, acc2[pp][0]);
                FFMA2(acc2[pp][1], xx[pp], w1, acc2[pp][1]);
                FFMA2(acc2[pp][2], xx[pp], w2, acc2[pp][2]);
            }
        }

#pragma unroll
        for (int pp = 0; pp < 4; pp++) {
            int pt = base + p0 + pp;
            if (pt < N0C) {
                __half* row = g_KVh + (size_t)pt * 128;
#pragma unroll
                for (int m = 0; m < 3; m++) {
                    int c = c0 + 2 * m;                 // pair never straddles c=32
                    int hidx = (c < 32) ? c : c + 32;   // V shifted to half-idx 64+
                    float2 v = unpack2(acc2[pp][m]);
                    *(__half2*)(row + hidx) = __floats2half2_rn(v.x, v.y);
                }
            }
        }
    } else if (blockIdx.x < KV_BLOCKS + Q_BLOCKS) {
        // ---------------- Q: [64 pts, 64 in] x [64, 32 out] ----------------
        float (*Ws)[32] = (float (*)[32])smem;
        float* Bs       = smem + 64 * 32;
        float (*Xs)[68] = (float (*)[68])(smem + 64 * 32 + 32);

        for (int idx = t; idx < 64 * 32; idx += 256)
            (&Ws[0][0])[idx] = Wq[idx];
        if (t < 32) Bs[t] = bq[t];

        const int base = (blockIdx.x - KV_BLOCKS) * 64;
        for (int idx = t; idx < 64 * 64; idx += 256) {
            int p = idx >> 6, i = idx & 63;
            int pt = base + p;
            Xs[i][p] = (pt < N1C) ? feats1[(size_t)pt * 64 + i] : 0.0f;
        }
        __syncthreads();

        const int tc = t & 15;
        const int tp = t >> 4;
        const int c0 = tc * 2;          // even
        const int p0 = tp * 4;

        unsigned long long acc2[4];
        {
            unsigned long long b = pack2(Bs[c0], Bs[c0 + 1]);
#pragma unroll
            for (int pp = 0; pp < 4; pp++) acc2[pp] = b;
        }

#pragma unroll 8
        for (int i = 0; i < 64; i++) {
            const float4 xv = *(const float4*)&Xs[i][p0];
            const unsigned long long w = *(const unsigned long long*)&Ws[i][c0];
            unsigned long long xx[4];
            xx[0] = pack2(xv.x, xv.x); xx[1] = pack2(xv.y, xv.y);
            xx[2] = pack2(xv.z, xv.z); xx[3] = pack2(xv.w, xv.w);
#pragma unroll
            for (int pp = 0; pp < 4; pp++)
                FFMA2(acc2[pp], xx[pp], w, acc2[pp]);
        }

#pragma unroll
        for (int pp = 0; pp < 4; pp++) {
            int pt = base + p0 + pp;
            if (pt < N1C) {
                float2 v = unpack2(acc2[pp]);
                *(float2*)(g_Q + (size_t)pt * 32 + c0) = v;
            }
        }
    } else {
        // ---------------- knn_idxs passthrough (int -> float) ----------------
        int b = blockIdx.x - KV_BLOCKS - Q_BLOCKS;
        int stride = (gridDim.x - KV_BLOCKS - Q_BLOCKS) * 256;
        for (int i = b * 256 + t; i < tailN; i += stride)
            outTail[i] = (float)knn[i];
    }
}

// ---------------------------------------------------------------------------
// Attention: ONE warp per query, 8 queries per 256-thread block.
// Phase A: each lane computes one full logit (row r, head h); lanes map so each
//   LDG.128 touches 8 distinct 128B lines with no replays.
// Phase B: 16 coalesced half2 row reads (1 line per iter per warp).
// ---------------------------------------------------------------------------
__global__ __launch_bounds__(256) void attn_kernel(
    const float* __restrict__ coords1,
    const int*   __restrict__ knn,
    const float* __restrict__ Wv,
    float*       __restrict__ out)
{
    const int l = threadIdx.x & 31;
    const int n = blockIdx.x * 8 + (threadIdx.x >> 5);  // N1C % 8 == 0

    // neighbor indices: lanes 0..15 hold idx[l]
    int myidx = 0;
    if (l < 16) myidx = knn[(size_t)n * 16 + l];

    const int h    = l & 3;        // head for phase A
    const int rsub = l >> 2;       // row sub-index (0..7)

    // q[h*8 .. h*8+7] (fp32), 2 LDG.128 (1 line each, broadcast within warp)
    const float4 q0 = *(const float4*)(g_Q + (size_t)n * 32 + h * 8);
    const float4 q1 = *(const float4*)(g_Q + (size_t)n * 32 + h * 8 + 4);

    const int j0 = __shfl_sync(0xffffffffu, myidx, rsub);
    const int j1 = __shfl_sync(0xffffffffu, myidx, 8 + rsub);

    // K chunks: 8 halves (16B) at row j, head h
    const uint4 kc0 = *(const uint4*)(g_KVh + (size_t)j0 * 128 + h * 8);
    const uint4 kc1 = *(const uint4*)(g_KVh + (size_t)j1 * 128 + h * 8);

    float logit0, logit1;
    {
        const __half2* kh = (const __half2*)&kc0;
        float2 a = __half22float2(kh[0]), b = __half22float2(kh[1]);
        float2 c = __half22float2(kh[2]), d = __half22float2(kh[3]);
        logit0 = a.x * q0.x + a.y * q0.y + b.x * q0.z + b.y * q0.w
               + c.x * q1.x + c.y * q1.y + d.x * q1.z + d.y * q1.w;
    }
    {
        const __half2* kh = (const __half2*)&kc1;
        float2 a = __half22float2(kh[0]), b = __half22float2(kh[1]);
        float2 c = __half22float2(kh[2]), d = __half22float2(kh[3]);
        logit1 = a.x * q0.x + a.y * q0.y + b.x * q0.z + b.y * q0.w
               + c.x * q1.x + c.y * q1.y + d.x * q1.z + d.y * q1.w;
    }
    logit0 *= 0.35355339059327373f;
    logit1 *= 0.35355339059327373f;

    // softmax across 16 rows of this head: lanes {h, h+4, ..., h+28} x 2 regs
    float m = fmaxf(logit0, logit1);
    m = fmaxf(m, __shfl_xor_sync(0xffffffffu, m, 4));
    m = fmaxf(m, __shfl_xor_sync(0xffffffffu, m, 8));
    m = fmaxf(m, __shfl_xor_sync(0xffffffffu, m, 16));
    float e0 = __expf(logit0 - m);
    float e1 = __expf(logit1 - m);
    float s = e0 + e1;
    s += __shfl_xor_sync(0xffffffffu, s, 4);
    s += __shfl_xor_sync(0xffffffffu, s, 8);
    s += __shfl_xor_sync(0xffffffffu, s, 16);
    const float inv_s = __frcp_rn(s);
    const float a0 = e0 * inv_s;
    const float a1 = e1 * inv_s;

    // Phase B: lane owns output dims (2l, 2l+1); head of those dims = l>>3.
    const int hd = l >> 3;
    float accx = 0.0f, accy = 0.0f;
#pragma unroll
    for (int r = 0; r < 16; r++) {
        const int jr = __shfl_sync(0xffffffffu, myidx, r);
        const int src = ((r & 7) << 2) + hd;
        const float ar = __shfl_sync(0xffffffffu, (r < 8) ? a0 : a1, src);
        const __half2 v = *(const __half2*)(g_KVh + (size_t)jr * 128 + 64 + 2 * l);
        const float2 vf = __half22float2(v);
        accx = fmaf(ar, vf.x, accx);
        accy = fmaf(ar, vf.y, accy);
    }

    // subtract (coords1[n] @ Wv[64:67, :]) for my two dims
    const float c1x = coords1[(size_t)n * 3 + 0];
    const float c1y = coords1[(size_t)n * 3 + 1];
    const float c1z = coords1[(size_t)n * 3 + 2];
    const float2 wv0 = *(const float2*)(Wv + (size_t)64 * 64 + 2 * l);
    const float2 wv1 = *(const float2*)(Wv + (size_t)65 * 64 + 2 * l);
    const float2 wv2 = *(const float2*)(Wv + (size_t)66 * 64 + 2 * l);
    const float cvx = c1x * wv0.x + c1y * wv1.x + c1z * wv2.x;
    const float cvy = c1x * wv0.y + c1y * wv1.y + c1z * wv2.y;

    *(float2*)(out + (size_t)n * 64 + 2 * l) = make_float2(accx - cvx, accy - cvy);
}

extern "C" void kernel_launch(void* const* d_in, const int* in_sizes, int n_in,
                              void* d_out, int out_size)
{
    const float* coords0 = (const float*)d_in[0];
    const float* coords1 = (const float*)d_in[1];
    const float* feats0  = (const float*)d_in[2];
    const float* feats1  = (const float*)d_in[3];
    const int*   knn     = (const int*)  d_in[4];
    const float* Wq      = (const float*)d_in[5];
    const float* bq      = (const float*)d_in[6];
    const float* Wk      = (const float*)d_in[7];
    const float* bk      = (const float*)d_in[8];
    const float* Wv      = (const float*)d_in[9];
    const float* bv      = (const float*)d_in[10];
    float* out = (float*)d_out;

    int tail = out_size - N1C * DM;
    if (tail < 0) tail = 0;
    int copyBlocks = tail > 0 ? (tail + 1023) / 1024 : 0;

    prep_kernel<<<KV_BLOCKS + Q_BLOCKS + copyBlocks, 256>>>(
        feats0, coords0, Wk, bk, Wv, bv,
        feats1, Wq, bq,
        knn, out + (size_t)N1C * DM, tail);

    attn_kernel<<<N1C / 8, 256>>>(coords1, knn, Wv, out);
}